// round 1
// baseline (speedup 1.0000x reference)
#include <cuda_runtime.h>
#include <cuda_bf16.h>
#include <stdint.h>

#define BB   32
#define TT   20
#define HH   100
#define GG   300      // 3H
#define DD   200      // 2H
#define KK   200      // GEMM K
#define VV   32000

// ---------------- scratch (static device globals; no allocation) ----------------
__device__ float g_gx0f[BB*TT*GG];
__device__ float g_gx0b[BB*TT*GG];
__device__ float g_y0  [BB*TT*DD];
__device__ float g_gx1f[BB*TT*GG];
__device__ float g_gx1b[BB*TT*GG];
__device__ float g_y1  [BB*TT*DD];

// ---------------- kernel A: embedding gather (one-hot matmul == column gather) --
__global__ void gather_kernel(const int* __restrict__ x,
                              const float* __restrict__ Wf,
                              const float* __restrict__ Wb) {
    int tok = blockIdx.x;            // 0..639  (= b*20 + t)
    int v   = x[tok];
    int tid = threadIdx.x;           // 0..599
    if (tid < GG) g_gx0f[tok*GG + tid]        = Wf[tid*VV + v];
    else          g_gx0b[tok*GG + (tid-GG)]   = Wb[(tid-GG)*VV + v];
}

// ---------------- GRU kernel: one CTA per (dir, batch) -------------------------
// 300 active threads each own one gate row of W_hh in registers (100 floats),
// h lives in smem. 20 sequential steps with two barriers per step.
__global__ __launch_bounds__(320) void gru_kernel(
    const float* __restrict__ gxf, const float* __restrict__ gxb,
    const float* __restrict__ Whhf, const float* __restrict__ Whhb,
    const float* __restrict__ hidden, int hid_base,
    float* __restrict__ y, float* __restrict__ hout)
{
    int dir = blockIdx.x >> 5;
    int b   = blockIdx.x & 31;
    const float* gx  = dir ? gxb  : gxf;
    const float* Whh = dir ? Whhb : Whhf;
    int g = threadIdx.x;

    __shared__ __align__(16) float h_s[HH];
    __shared__ float gh_s[GG];
    __shared__ float gx_s[GG];

    float w[HH];
    if (g < GG) {
        #pragma unroll
        for (int k = 0; k < HH; k++) w[k] = Whh[g*HH + k];
    }
    if (g < HH) h_s[g] = hidden[(hid_base + dir)*BB*HH + b*HH + g];
    __syncthreads();

    for (int t = 0; t < TT; t++) {
        int tt = dir ? (TT-1-t) : t;
        float acc = 0.f, gxv = 0.f;
        if (g < GG) {
            gxv = gx[(b*TT + tt)*GG + g];
            const float4* h4 = reinterpret_cast<const float4*>(h_s);
            #pragma unroll
            for (int kk = 0; kk < HH/4; kk++) {
                float4 hv = h4[kk];
                acc += w[4*kk+0]*hv.x + w[4*kk+1]*hv.y
                     + w[4*kk+2]*hv.z + w[4*kk+3]*hv.w;
            }
            gh_s[g] = acc;
            gx_s[g] = gxv;
        }
        __syncthreads();   // all dot-reads of h_s done; gh/gx visible
        if (g < HH) {
            float r = 1.f/(1.f + __expf(-(gx_s[g]        + gh_s[g])));
            float z = 1.f/(1.f + __expf(-(gx_s[HH+g]     + gh_s[HH+g])));
            float n = tanhf(gx_s[2*HH+g] + r*gh_s[2*HH+g]);
            float hn = (1.f - z)*n + z*h_s[g];
            h_s[g] = hn;
            y[(b*TT + tt)*DD + dir*HH + g] = hn;
        }
        __syncthreads();   // new h visible for next step
    }
    if (g < HH) hout[(hid_base + dir)*BB*HH + b*HH + g] = h_s[g];
}

// ---------------- split-bf16 GEMM: C[M,N] = A[M,K] * B[N,K]^T  ------------------
// fp32 operands split into bf16 hi+lo; 3 mma passes (Ah*Bh + Al*Bh + Ah*Bl)
// give ~2^-16 relative error (well under the 1e-3 gate).
// CTA tile 128x128, K=200 fully resident in smem (padded stride 216 elems,
// conflict-free for ldmatrix). 8 warps as 4(m) x 2(n), warp tile 32x64.
#define BM 128
#define BN 128
#define KP 216
#define KC 13   // 13 * 16 = 208 >= 200 (cols 200..215 zero-padded)

__device__ __forceinline__ void ldsm4(uint32_t* r, uint32_t addr) {
    asm volatile("ldmatrix.sync.aligned.m8n8.x4.shared.b16 {%0,%1,%2,%3}, [%4];"
        : "=r"(r[0]), "=r"(r[1]), "=r"(r[2]), "=r"(r[3]) : "r"(addr));
}
__device__ __forceinline__ void mma16816(float* c, const uint32_t* a,
                                         uint32_t b0, uint32_t b1) {
    asm volatile("mma.sync.aligned.m16n8k16.row.col.f32.bf16.bf16.f32 "
        "{%0,%1,%2,%3}, {%4,%5,%6,%7}, {%8,%9}, {%0,%1,%2,%3};"
        : "+f"(c[0]), "+f"(c[1]), "+f"(c[2]), "+f"(c[3])
        : "r"(a[0]), "r"(a[1]), "r"(a[2]), "r"(a[3]), "r"(b0), "r"(b1));
}
__device__ __forceinline__ uint32_t pack_bf2(__nv_bfloat16 a, __nv_bfloat16 b) {
    __nv_bfloat162 t = __halves2bfloat162(a, b);
    return *reinterpret_cast<uint32_t*>(&t);
}

__global__ __launch_bounds__(256) void gemm3_kernel(
    const float* __restrict__ A, const float* __restrict__ Bm,
    float* __restrict__ C, int N, int ldc)
{
    extern __shared__ __align__(16) unsigned char smem_raw[];
    __nv_bfloat16* Ahi = reinterpret_cast<__nv_bfloat16*>(smem_raw);
    __nv_bfloat16* Alo = Ahi + BM*KP;
    __nv_bfloat16* Bhi = Alo + BM*KP;
    __nv_bfloat16* Blo = Bhi + BN*KP;

    int tid = threadIdx.x;
    int m0  = blockIdx.y * BM;
    int n0  = blockIdx.x * BN;

    // zero the K padding region (cols 200..215) in all 4 buffers
    for (int i = tid; i < BM*8; i += 256) {
        int row = i >> 3, c = (i & 7);
        reinterpret_cast<uint32_t*>(Ahi + row*KP + 200)[c] = 0u;
        reinterpret_cast<uint32_t*>(Alo + row*KP + 200)[c] = 0u;
        reinterpret_cast<uint32_t*>(Bhi + row*KP + 200)[c] = 0u;
        reinterpret_cast<uint32_t*>(Blo + row*KP + 200)[c] = 0u;
    }

    // load + split A tile (rows always valid: M = 640, grid.y = 5)
    for (int i = tid; i < BM*(KK/4); i += 256) {
        int row = i / (KK/4), c = (i % (KK/4)) * 4;
        float4 v = *reinterpret_cast<const float4*>(A + (m0+row)*KK + c);
        __nv_bfloat16 hx = __float2bfloat16(v.x), hy = __float2bfloat16(v.y);
        __nv_bfloat16 hz = __float2bfloat16(v.z), hw = __float2bfloat16(v.w);
        __nv_bfloat16 lx = __float2bfloat16(v.x - __bfloat162float(hx));
        __nv_bfloat16 ly = __float2bfloat16(v.y - __bfloat162float(hy));
        __nv_bfloat16 lz = __float2bfloat16(v.z - __bfloat162float(hz));
        __nv_bfloat16 lw = __float2bfloat16(v.w - __bfloat162float(hw));
        uint32_t* ph = reinterpret_cast<uint32_t*>(Ahi + row*KP + c);
        uint32_t* pl = reinterpret_cast<uint32_t*>(Alo + row*KP + c);
        ph[0] = pack_bf2(hx, hy); ph[1] = pack_bf2(hz, hw);
        pl[0] = pack_bf2(lx, ly); pl[1] = pack_bf2(lz, lw);
    }
    // load + split B tile (guard N tail)
    for (int i = tid; i < BN*(KK/4); i += 256) {
        int row = i / (KK/4), c = (i % (KK/4)) * 4;
        float4 v = make_float4(0.f,0.f,0.f,0.f);
        if (n0 + row < N)
            v = *reinterpret_cast<const float4*>(Bm + (n0+row)*KK + c);
        __nv_bfloat16 hx = __float2bfloat16(v.x), hy = __float2bfloat16(v.y);
        __nv_bfloat16 hz = __float2bfloat16(v.z), hw = __float2bfloat16(v.w);
        __nv_bfloat16 lx = __float2bfloat16(v.x - __bfloat162float(hx));
        __nv_bfloat16 ly = __float2bfloat16(v.y - __bfloat162float(hy));
        __nv_bfloat16 lz = __float2bfloat16(v.z - __bfloat162float(hz));
        __nv_bfloat16 lw = __float2bfloat16(v.w - __bfloat162float(hw));
        uint32_t* ph = reinterpret_cast<uint32_t*>(Bhi + row*KP + c);
        uint32_t* pl = reinterpret_cast<uint32_t*>(Blo + row*KP + c);
        ph[0] = pack_bf2(hx, hy); ph[1] = pack_bf2(hz, hw);
        pl[0] = pack_bf2(lx, ly); pl[1] = pack_bf2(lz, lw);
    }
    __syncthreads();

    int wid = tid >> 5, lane = tid & 31;
    int wm = wid & 3;          // m block of 32
    int wn = wid >> 2;         // n block of 64
    int lr = lane & 7, lq = lane >> 3;

    // ldmatrix lane addressing (A: x4 covers 16x16; B: x4 covers n16 x k16)
    uint32_t aRow = wm*32 + (lq & 1)*8 + lr;
    uint32_t aCol = (lq >> 1)*8;
    uint32_t bRow = wn*64 + (lq >> 1)*8 + lr;
    uint32_t bCol = (lq & 1)*8;

    uint32_t aHiB = (uint32_t)__cvta_generic_to_shared(Ahi) + (aRow*KP + aCol)*2;
    uint32_t aLoB = (uint32_t)__cvta_generic_to_shared(Alo) + (aRow*KP + aCol)*2;
    uint32_t bHiB = (uint32_t)__cvta_generic_to_shared(Bhi) + (bRow*KP + bCol)*2;
    uint32_t bLoB = (uint32_t)__cvta_generic_to_shared(Blo) + (bRow*KP + bCol)*2;

    float acc[2][8][4];
    #pragma unroll
    for (int mt = 0; mt < 2; mt++)
        #pragma unroll
        for (int nt = 0; nt < 8; nt++)
            #pragma unroll
            for (int j = 0; j < 4; j++) acc[mt][nt][j] = 0.f;

    #pragma unroll
    for (int kc = 0; kc < KC; kc++) {
        uint32_t kOff = (uint32_t)(kc*16) * 2;
        uint32_t ah[2][4], al[2][4], bh[4][4], bl[4][4];
        #pragma unroll
        for (int mt = 0; mt < 2; mt++) {
            uint32_t o = (uint32_t)(mt*16*KP)*2 + kOff;
            ldsm4(ah[mt], aHiB + o);
            ldsm4(al[mt], aLoB + o);
        }
        #pragma unroll
        for (int nt2 = 0; nt2 < 4; nt2++) {
            uint32_t o = (uint32_t)(nt2*16*KP)*2 + kOff;
            ldsm4(bh[nt2], bHiB + o);
            ldsm4(bl[nt2], bLoB + o);
        }
        #pragma unroll
        for (int mt = 0; mt < 2; mt++)
            #pragma unroll
            for (int nt = 0; nt < 8; nt++) {
                const uint32_t* bhp = &bh[nt >> 1][(nt & 1)*2];
                const uint32_t* blp = &bl[nt >> 1][(nt & 1)*2];
                mma16816(acc[mt][nt], ah[mt], bhp[0], bhp[1]);  // Ah*Bh
                mma16816(acc[mt][nt], al[mt], bhp[0], bhp[1]);  // Al*Bh
                mma16816(acc[mt][nt], ah[mt], blp[0], blp[1]);  // Ah*Bl
            }
    }

    // epilogue
    int r0 = m0 + wm*32 + (lane >> 2);
    int c0 = n0 + wn*64 + ((lane & 3)*2);
    #pragma unroll
    for (int mt = 0; mt < 2; mt++)
        #pragma unroll
        for (int nt = 0; nt < 8; nt++) {
            int row = r0 + mt*16;
            int col = c0 + nt*8;
            if (col < N) {
                *reinterpret_cast<float2*>(C + (size_t)row*ldc + col) =
                    make_float2(acc[mt][nt][0], acc[mt][nt][1]);
                *reinterpret_cast<float2*>(C + (size_t)(row+8)*ldc + col) =
                    make_float2(acc[mt][nt][2], acc[mt][nt][3]);
            }
        }
}

// ---------------- launch ----------------
extern "C" void kernel_launch(void* const* d_in, const int* in_sizes, int n_in,
                              void* d_out, int out_size) {
    const int*   x      = (const int*)  d_in[0];
    const float* hidden = (const float*)d_in[1];
    const float* Wih0f  = (const float*)d_in[2];
    const float* Whh0f  = (const float*)d_in[3];
    const float* Wih0b  = (const float*)d_in[4];
    const float* Whh0b  = (const float*)d_in[5];
    const float* Wih1f  = (const float*)d_in[6];
    const float* Whh1f  = (const float*)d_in[7];
    const float* Wih1b  = (const float*)d_in[8];
    const float* Whh1b  = (const float*)d_in[9];
    const float* Wlin   = (const float*)d_in[10];

    float* out  = (float*)d_out;
    float* hout = out + (out_size - 4*BB*HH);   // h_out tail: [4][32][100]

    void *p_gx0f, *p_gx0b, *p_y0, *p_gx1f, *p_gx1b, *p_y1;
    cudaGetSymbolAddress(&p_gx0f, g_gx0f);
    cudaGetSymbolAddress(&p_gx0b, g_gx0b);
    cudaGetSymbolAddress(&p_y0,   g_y0);
    cudaGetSymbolAddress(&p_gx1f, g_gx1f);
    cudaGetSymbolAddress(&p_gx1b, g_gx1b);
    cudaGetSymbolAddress(&p_y1,   g_y1);

    const size_t SMEMSZ = (size_t)(2*BM + 2*BN) * KP * 2;  // 221184 B
    cudaFuncSetAttribute(gemm3_kernel,
                         cudaFuncAttributeMaxDynamicSharedMemorySize, (int)SMEMSZ);

    // 1. embedding gather
    gather_kernel<<<BB*TT, 2*GG>>>(x, Wih0f, Wih0b);

    // 2. GRU layer 0 (both directions)
    gru_kernel<<<64, 320>>>((const float*)p_gx0f, (const float*)p_gx0b,
                            Whh0f, Whh0b, hidden, 0,
                            (float*)p_y0, hout);

    // 3. layer-1 input projections: gx1{f,b} = y0 @ W_ih_l1{f,b}^T
    gemm3_kernel<<<dim3(3,5), 256, SMEMSZ>>>((const float*)p_y0, Wih1f,
                                             (float*)p_gx1f, GG, GG);
    gemm3_kernel<<<dim3(3,5), 256, SMEMSZ>>>((const float*)p_y0, Wih1b,
                                             (float*)p_gx1b, GG, GG);

    // 4. GRU layer 1
    gru_kernel<<<64, 320>>>((const float*)p_gx1f, (const float*)p_gx1b,
                            Whh1f, Whh1b, hidden, 2,
                            (float*)p_y1, hout);

    // 5. final projection: prediction = y1 @ W_lin^T   [640 x 32000]
    gemm3_kernel<<<dim3((VV + BN - 1)/BN, 5), 256, SMEMSZ>>>(
        (const float*)p_y1, Wlin, out, VV, VV);
}